// round 1
// baseline (speedup 1.0000x reference)
#include <cuda_runtime.h>
#include <math.h>

#define D 768
#define K2 1536
#define BATCH 4
#define TSEQ 2048
#define NLEV 11
#define EPSV 1.1920928955078125e-07f

// ---------------- scratch (device globals; no allocation allowed) ----------------
// summaries S_1..S_11: 4*768*(1024+512+...+1) = 6,288,384 floats
__device__ __align__(256) float g_S[6288384 + 64];
__device__ __align__(256) float g_ctxA[6291456];
__device__ __align__(256) float g_ctxB[6291456];
__device__ __align__(256) float g_XP[6291456];
__device__ __align__(256) float g_GT[6291456];
__device__ __align__(256) float g_XN[6291456];
__device__ __align__(256) float g_SPK[6291456];

// ---------------- helpers ----------------
__device__ __forceinline__ float blockReduceSum256(float v) {
    __shared__ float sh[8];
    __shared__ float s_tot;
    int lane = threadIdx.x & 31;
    int wid = threadIdx.x >> 5;
    #pragma unroll
    for (int o = 16; o > 0; o >>= 1) v += __shfl_down_sync(0xffffffffu, v, o);
    if (lane == 0) sh[wid] = v;
    __syncthreads();
    if (wid == 0) {
        float t = (lane < 8) ? sh[lane] : 0.0f;
        #pragma unroll
        for (int o = 4; o > 0; o >>= 1) t += __shfl_down_sync(0xffffffffu, t, o);
        if (lane == 0) s_tot = t;
    }
    __syncthreads();
    return s_tot;
}

// ---------------- GEMM: out[r][n] = act( in[r] @ W + b ) ----------------
// in[r][k] = (k < D) ? A0[r*ldA0 + k] : A1[r*ldA1 + (k-D)]
// blockIdx.z == 0: proj (no act) -> outP ; == 1: sel (sigmoid) -> outG
__global__ void gemm_dual(const float* __restrict__ A0, int ldA0,
                          const float* __restrict__ A1, int ldA1,
                          const float* __restrict__ Wp, const float* __restrict__ bp,
                          const float* __restrict__ Ws, const float* __restrict__ bs,
                          float* __restrict__ outP, float* __restrict__ outG, int M) {
    const bool isSel = (blockIdx.z == 1);
    const float* __restrict__ W = isSel ? Ws : Wp;
    const float* __restrict__ bias = isSel ? bs : bp;
    float* __restrict__ out = isSel ? outG : outP;

    __shared__ float As[16][64];
    __shared__ float Bs[16][64];

    const int tid = threadIdx.x;
    const int tx = tid & 15;
    const int ty = tid >> 4;
    const int rowBase = blockIdx.y * 64;
    const int nBase = blockIdx.x * 64;

    const int a_row = tid >> 2;          // 0..63
    const int a_k4 = (tid & 3) * 4;      // 0,4,8,12
    const int w_k = tid >> 4;            // 0..15
    const int w_n4 = (tid & 15) * 4;     // 0..60

    float acc[4][4];
    #pragma unroll
    for (int i = 0; i < 4; i++)
        #pragma unroll
        for (int j = 0; j < 4; j++) acc[i][j] = 0.0f;

    for (int k0 = 0; k0 < K2; k0 += 16) {
        const float* Asrc;
        int ld, kcol;
        if (k0 < D) { Asrc = A0; ld = ldA0; kcol = k0; }
        else        { Asrc = A1; ld = ldA1; kcol = k0 - D; }

        float4 av = make_float4(0.f, 0.f, 0.f, 0.f);
        int gr = rowBase + a_row;
        if (gr < M)
            av = *reinterpret_cast<const float4*>(Asrc + (size_t)gr * ld + kcol + a_k4);
        As[a_k4 + 0][a_row] = av.x;
        As[a_k4 + 1][a_row] = av.y;
        As[a_k4 + 2][a_row] = av.z;
        As[a_k4 + 3][a_row] = av.w;

        float4 wv = *reinterpret_cast<const float4*>(W + (size_t)(k0 + w_k) * D + nBase + w_n4);
        *reinterpret_cast<float4*>(&Bs[w_k][w_n4]) = wv;

        __syncthreads();
        #pragma unroll
        for (int kk = 0; kk < 16; kk++) {
            float a[4], b[4];
            *reinterpret_cast<float4*>(a) = *reinterpret_cast<const float4*>(&As[kk][ty * 4]);
            *reinterpret_cast<float4*>(b) = *reinterpret_cast<const float4*>(&Bs[kk][tx * 4]);
            #pragma unroll
            for (int i = 0; i < 4; i++)
                #pragma unroll
                for (int j = 0; j < 4; j++)
                    acc[i][j] += a[i] * b[j];
        }
        __syncthreads();
    }

    #pragma unroll
    for (int i = 0; i < 4; i++) {
        int gr = rowBase + ty * 4 + i;
        if (gr >= M) continue;
        #pragma unroll
        for (int j = 0; j < 4; j++) {
            int n = nBase + tx * 4 + j;
            float v = acc[i][j] + bias[n];
            if (isSel) v = 1.0f / (1.0f + expf(-v));
            out[(size_t)gr * D + n] = v;
        }
    }
}

// ---------------- RMSNorm: xn = xp * rsqrt(mean(xp^2)+eps) * w ----------------
__global__ void rmsnorm_k(const float* __restrict__ xp, const float* __restrict__ w,
                          float* __restrict__ xn) {
    const int r = blockIdx.x;
    const float* row = xp + (size_t)r * D;
    float ss = 0.0f;
    for (int d = threadIdx.x; d < D; d += 256) { float v = row[d]; ss += v * v; }
    float tot = blockReduceSum256(ss);
    float inv = 1.0f / sqrtf(tot / (float)D + EPSV);
    for (int d = threadIdx.x; d < D; d += 256)
        xn[(size_t)r * D + d] = row[d] * inv * w[d];
}

// ---------------- LIF spikes: v[t] = sum_{j<min(K, t+1)} tau^j x[t-j]; spike = v>=th ----
__global__ void lif_k(const float* __restrict__ xn, float* __restrict__ spk,
                      const float* __restrict__ tau_a, const float* __restrict__ th_a,
                      int Tn, int total) {
    int idx = blockIdx.x * 256 + threadIdx.x;
    if (idx >= total) return;
    int d = idx % D;
    int r = idx / D;          // r = b*Tn + t
    int t = r % Tn;
    int K = Tn < 64 ? Tn : 64;
    int jmax = (t + 1 < K) ? (t + 1) : K;
    float tau = tau_a[d];
    float v = 0.0f, p = 1.0f;
    const float* base = xn + (size_t)r * D + d;
    for (int j = 0; j < jmax; j++) {
        v += p * base[-(ptrdiff_t)j * D];
        p *= tau;
    }
    spk[idx] = (v >= th_a[d]) ? 1.0f : 0.0f;
}

// ---------------- combines ----------------
// up: S_out[r] = g*(xp + spk/denom) + (1-g)*0.5*(cur[r][0:D] + cur[r][D:2D])
__global__ void combine_up(const float* __restrict__ xp, const float* __restrict__ gt,
                           const float* __restrict__ spk, const float* __restrict__ cur,
                           float* __restrict__ outS) {
    const int r = blockIdx.x;
    float s = 0.0f;
    for (int d = threadIdx.x; d < D; d += 256) s += spk[(size_t)r * D + d];
    float denom = blockReduceSum256(s);
    denom = denom > 1.0f ? denom : 1.0f;
    for (int d = threadIdx.x; d < D; d += 256) {
        size_t o = (size_t)r * D + d;
        float g = gt[o];
        float lifout = xp[o] + spk[o] / denom;
        float res = 0.5f * (cur[(size_t)r * K2 + d] + cur[(size_t)r * K2 + D + d]);
        outS[o] = g * lifout + (1.0f - g) * res;
    }
}

// down: ctxN[2r] = ctx[r]; ctxN[2r+1] = g*(xp + spk/denom) + (1-g)*ctx[r]
__global__ void combine_down(const float* __restrict__ xp, const float* __restrict__ gt,
                             const float* __restrict__ spk, const float* __restrict__ ctx,
                             float* __restrict__ ctxN) {
    const int r = blockIdx.x;
    float s = 0.0f;
    for (int d = threadIdx.x; d < D; d += 256) s += spk[(size_t)r * D + d];
    float denom = blockReduceSum256(s);
    denom = denom > 1.0f ? denom : 1.0f;
    for (int d = threadIdx.x; d < D; d += 256) {
        size_t o = (size_t)r * D + d;
        float c = ctx[o];
        float g = gt[o];
        float lifout = xp[o] + spk[o] / denom;
        float cr = g * lifout + (1.0f - g) * c;
        ctxN[(size_t)(2 * r) * D + d] = c;
        ctxN[(size_t)(2 * r + 1) * D + d] = cr;
    }
}

// leaf: out[r] = g*(xp + spk/denom) + (1-g)*x[r]
__global__ void combine_leaf(const float* __restrict__ xp, const float* __restrict__ gt,
                             const float* __restrict__ spk, const float* __restrict__ x,
                             float* __restrict__ out) {
    const int r = blockIdx.x;
    float s = 0.0f;
    for (int d = threadIdx.x; d < D; d += 256) s += spk[(size_t)r * D + d];
    float denom = blockReduceSum256(s);
    denom = denom > 1.0f ? denom : 1.0f;
    for (int d = threadIdx.x; d < D; d += 256) {
        size_t o = (size_t)r * D + d;
        float g = gt[o];
        float lifout = xp[o] + spk[o] / denom;
        out[o] = g * lifout + (1.0f - g) * x[o];
    }
}

__global__ void zero_k(float* __restrict__ p, int n) {
    int i = blockIdx.x * 256 + threadIdx.x;
    if (i < n) p[i] = 0.0f;
}

// ---------------- launcher ----------------
extern "C" void kernel_launch(void* const* d_in, const int* in_sizes, int n_in,
                              void* d_out, int out_size) {
    const float* x     = (const float*)d_in[0];
    const float* upW   = (const float*)d_in[1];
    const float* upB   = (const float*)d_in[2];
    const float* upSW  = (const float*)d_in[3];
    const float* upSB  = (const float*)d_in[4];
    const float* upNW  = (const float*)d_in[5];
    const float* upTH  = (const float*)d_in[6];
    const float* upTAU = (const float*)d_in[7];
    const float* dnW   = (const float*)d_in[8];
    const float* dnB   = (const float*)d_in[9];
    const float* dnSW  = (const float*)d_in[10];
    const float* dnSB  = (const float*)d_in[11];
    const float* dnNW  = (const float*)d_in[12];
    const float* dnTH  = (const float*)d_in[13];
    const float* dnTAU = (const float*)d_in[14];
    const float* lfSW  = (const float*)d_in[15];
    const float* lfSB  = (const float*)d_in[16];
    const float* lfW   = (const float*)d_in[17];
    const float* lfB   = (const float*)d_in[18];
    const float* lfNW  = (const float*)d_in[19];
    const float* lfTH  = (const float*)d_in[20];
    const float* lfTAU = (const float*)d_in[21];
    float* out = (float*)d_out;

    float *S, *cA, *cB, *XP, *GT, *XN, *SPK;
    cudaGetSymbolAddress((void**)&S, g_S);
    cudaGetSymbolAddress((void**)&cA, g_ctxA);
    cudaGetSymbolAddress((void**)&cB, g_ctxB);
    cudaGetSymbolAddress((void**)&XP, g_XP);
    cudaGetSymbolAddress((void**)&GT, g_GT);
    cudaGetSymbolAddress((void**)&XN, g_XN);
    cudaGetSymbolAddress((void**)&SPK, g_SPK);

    // summary offsets: S_k has BATCH*(TSEQ>>k)*D floats, k = 1..11
    size_t soff[NLEV + 1];
    soff[1] = 0;
    for (int k = 1; k < NLEV; k++)
        soff[k + 1] = soff[k] + (size_t)BATCH * (TSEQ >> k) * D;

    // ---- up pass ----
    const float* cur = x;
    int Tl = TSEQ;
    for (int l = 0; l < NLEV; l++) {
        int Tn = Tl >> 1;
        int M = BATCH * Tn;
        float* Sout = S + soff[l + 1];
        dim3 gg(D / 64, (M + 63) / 64, 2);
        gemm_dual<<<gg, 256>>>(cur, K2, cur + D, K2,
                               upW + (size_t)l * K2 * D, upB + (size_t)l * D,
                               upSW + (size_t)l * K2 * D, upSB + (size_t)l * D,
                               XP, GT, M);
        rmsnorm_k<<<M, 256>>>(XP, upNW + (size_t)l * D, XN);
        int tot = M * D;
        lif_k<<<(tot + 255) / 256, 256>>>(XN, SPK, upTAU + (size_t)l * D,
                                          upTH + (size_t)l * D, Tn, tot);
        combine_up<<<M, 256>>>(XP, GT, SPK, cur, Sout);
        cur = Sout;
        Tl = Tn;
    }

    // ---- down pass ----
    zero_k<<<(BATCH * D + 255) / 256, 256>>>(cA, BATCH * D);
    float* ctx = cA;
    float* ctxN = cB;
    int n = 1;
    for (int l = NLEV; l >= 1; l--) {
        int i = l - 1;
        int M = BATCH * n;
        const float* child = (i == 0) ? x : (S + soff[i]);
        dim3 gg(D / 64, (M + 63) / 64, 2);
        gemm_dual<<<gg, 256>>>(ctx, D, child, 2 * D,
                               dnW + (size_t)i * K2 * D, dnB + (size_t)i * D,
                               dnSW + (size_t)i * K2 * D, dnSB + (size_t)i * D,
                               XP, GT, M);
        rmsnorm_k<<<M, 256>>>(XP, dnNW + (size_t)i * D, XN);
        int tot = M * D;
        lif_k<<<(tot + 255) / 256, 256>>>(XN, SPK, dnTAU + (size_t)i * D,
                                          dnTH + (size_t)i * D, n, tot);
        combine_down<<<M, 256>>>(XP, GT, SPK, ctx, ctxN);
        float* tmp = ctx; ctx = ctxN; ctxN = tmp;
        n <<= 1;
    }

    // ---- leaf fusion ---- (n == TSEQ now; ctx holds final context)
    {
        int M = BATCH * TSEQ;
        dim3 gg(D / 64, (M + 63) / 64, 2);
        gemm_dual<<<gg, 256>>>(x, D, ctx, D,
                               lfW, lfB, lfSW, lfSB, XP, GT, M);
        rmsnorm_k<<<M, 256>>>(XP, lfNW, XN);
        int tot = M * D;
        lif_k<<<(tot + 255) / 256, 256>>>(XN, SPK, lfTAU, lfTH, TSEQ, tot);
        combine_leaf<<<M, 256>>>(XP, GT, SPK, x, out);
    }
}

// round 5
// speedup vs baseline: 2.5649x; 2.5649x over previous
#include <cuda_runtime.h>
#include <math.h>
#include <stdint.h>

#define D 768
#define K2 1536
#define BATCH 4
#define TSEQ 2048
#define NLEV 11
#define EPSV 1.1920928955078125e-07f

// ---------------- scratch (device globals) ----------------
__device__ __align__(256) float g_S[6288384 + 64];
__device__ __align__(256) float g_ctxA[6291456];
__device__ __align__(256) float g_ctxB[6291456];
__device__ __align__(256) float g_XP[6291456];
__device__ __align__(256) float g_GT[6291456];
__device__ __align__(256) float g_XN[6291456];
__device__ __align__(256) float g_SPK[6291456];

// ---------------- helpers ----------------
__device__ __forceinline__ uint32_t smem_u32(const void* p) {
    uint32_t a;
    asm("{ .reg .u64 t; cvta.to.shared.u64 t, %1; cvt.u32.u64 %0, t; }" : "=r"(a) : "l"(p));
    return a;
}
__device__ __forceinline__ uint32_t f2tf32(float f) {
    uint32_t r;
    asm("cvt.rna.tf32.f32 %0, %1;" : "=r"(r) : "f"(f));
    return r;
}

// ================= TF32 mma.sync GEMM =================
// out[r][n] = act( concat(A0[r], A1[r]) @ W + bias )
// W is [K2][D] row-major (k-major), consumed as col-major B fragments.
// blockIdx.x in [0, ntiles): proj -> outP ; [ntiles, 2*ntiles): sel (sigmoid) -> outG
template <int BN, int WROWS>
__global__ void __launch_bounds__(256, 1)
gemm_mma(const float* __restrict__ A0, int ldA0,
         const float* __restrict__ A1, int ldA1,
         const float* __restrict__ Wp, const float* __restrict__ Ws,
         const float* __restrict__ bp, const float* __restrict__ bs,
         float* __restrict__ outP, float* __restrict__ outG, int M) {
    constexpr int BM = 128, BK = 32, STAGES = 3;
    constexpr int LDA = BK + 4;            // 36: A frag LDS conflict-free
    constexpr int LDB = BN + 8;            // ≡8 mod 32: B frag LDS conflict-free
    constexpr int A_ELE = BM * LDA;
    constexpr int B_ELE = BK * LDB;
    constexpr int WCOLS = 8 / WROWS;
    constexpr int WARP_M = BM / WROWS;
    constexpr int MT = WARP_M / 16;
    constexpr int NTL = 4;                 // warp covers 32 cols = 4 x n8
    constexpr int ACHUNK = BM * 8 / 256;   // cp.async iters for A
    constexpr int BCHUNK = (BK * BN / 4) / 256;
    constexpr int NITER = K2 / BK;         // 48

    extern __shared__ float sm[];
    float* sA = sm;
    float* sB = sm + STAGES * A_ELE;
    const uint32_t sA_u = smem_u32(sA);
    const uint32_t sB_u = smem_u32(sB);

    const int tid = threadIdx.x;
    const int wid = tid >> 5, lane = tid & 31;
    const int g = lane >> 2, tig = lane & 3;
    const int warpM = wid % WROWS, warpN = wid / WROWS;

    const int ntiles = 768 / BN;
    const bool isSel = ((int)blockIdx.x >= ntiles);
    const int nbase = (isSel ? blockIdx.x - ntiles : blockIdx.x) * BN;
    const float* __restrict__ W = isSel ? Ws : Wp;
    const float* __restrict__ bias = isSel ? bs : bp;
    float* __restrict__ out = isSel ? outG : outP;
    const int rowBase = blockIdx.y * BM;

    float c[MT][NTL][4];
    #pragma unroll
    for (int mt = 0; mt < MT; mt++)
        #pragma unroll
        for (int nt = 0; nt < NTL; nt++)
            #pragma unroll
            for (int j = 0; j < 4; j++) c[mt][nt][j] = 0.0f;

    auto issue = [&](int it) {
        const int s = it % STAGES;
        // ---- A: BM rows x 32 floats ----
        const float* src; int ld, kc;
        if (it < 24) { src = A0; ld = ldA0; kc = it * BK; }
        else         { src = A1; ld = ldA1; kc = (it - 24) * BK; }
        #pragma unroll
        for (int i = 0; i < ACHUNK; i++) {
            int idx = tid + i * 256;
            int row = idx >> 3, q = idx & 7;
            int gr = rowBase + row;
            uint32_t dst = sA_u + (uint32_t)(s * A_ELE + row * LDA + q * 4) * 4u;
            const float* gsrc = src + (size_t)gr * ld + kc + q * 4;
            int sz = (gr < M) ? 16 : 0;
            asm volatile("cp.async.cg.shared.global [%0], [%1], 16, %2;"
                         :: "r"(dst), "l"(gsrc), "r"(sz));
        }
        // ---- B: 32 k-rows x BN floats from W[k][n] ----
        const int kb = it * BK;
        #pragma unroll
        for (int i = 0; i < BCHUNK; i++) {
            int idx = tid + i * 256;
            int row = idx / (BN / 4), q = idx % (BN / 4);
            uint32_t dst = sB_u + (uint32_t)(s * B_ELE + row * LDB + q * 4) * 4u;
            const float* gsrc = W + (size_t)(kb + row) * D + nbase + q * 4;
            asm volatile("cp.async.cg.shared.global [%0], [%1], 16, 16;"
                         :: "r"(dst), "l"(gsrc));
        }
        asm volatile("cp.async.commit_group;" ::: "memory");
    };

    #pragma unroll
    for (int it = 0; it < STAGES - 1; it++) issue(it);

    for (int it = 0; it < NITER; it++) {
        if (it + STAGES - 1 < NITER) issue(it + STAGES - 1);
        else asm volatile("cp.async.commit_group;" ::: "memory");
        asm volatile("cp.async.wait_group %0;" :: "n"(STAGES - 1));
        __syncthreads();

        const int s = it % STAGES;
        const float* As_ = sA + s * A_ELE;
        const float* Bs_ = sB + s * B_ELE;
        #pragma unroll
        for (int kk = 0; kk < 4; kk++) {
            uint32_t a[MT][4];
            #pragma unroll
            for (int mt = 0; mt < MT; mt++) {
                int r = warpM * WARP_M + mt * 16 + g;
                int cx = kk * 8 + tig;
                a[mt][0] = f2tf32(As_[r * LDA + cx]);
                a[mt][1] = f2tf32(As_[(r + 8) * LDA + cx]);
                a[mt][2] = f2tf32(As_[r * LDA + cx + 4]);
                a[mt][3] = f2tf32(As_[(r + 8) * LDA + cx + 4]);
            }
            uint32_t b[NTL][2];
            #pragma unroll
            for (int nt = 0; nt < NTL; nt++) {
                int n = warpN * 32 + nt * 8 + g;
                b[nt][0] = f2tf32(Bs_[(kk * 8 + tig) * LDB + n]);
                b[nt][1] = f2tf32(Bs_[(kk * 8 + tig + 4) * LDB + n]);
            }
            #pragma unroll
            for (int mt = 0; mt < MT; mt++)
                #pragma unroll
                for (int nt = 0; nt < NTL; nt++)
                    asm volatile(
                        "mma.sync.aligned.m16n8k8.row.col.f32.tf32.tf32.f32 "
                        "{%0,%1,%2,%3}, {%4,%5,%6,%7}, {%8,%9}, {%0,%1,%2,%3};"
                        : "+f"(c[mt][nt][0]), "+f"(c[mt][nt][1]),
                          "+f"(c[mt][nt][2]), "+f"(c[mt][nt][3])
                        : "r"(a[mt][0]), "r"(a[mt][1]), "r"(a[mt][2]), "r"(a[mt][3]),
                          "r"(b[nt][0]), "r"(b[nt][1]));
        }
        __syncthreads();
    }

    // ---- epilogue: bias (+sigmoid), fp32 store ----
    #pragma unroll
    for (int mt = 0; mt < MT; mt++) {
        #pragma unroll
        for (int i = 0; i < 2; i++) {
            int gr = rowBase + warpM * WARP_M + mt * 16 + g + i * 8;
            if (gr >= M) continue;
            #pragma unroll
            for (int nt = 0; nt < NTL; nt++) {
                int col = nbase + warpN * 32 + nt * 8 + tig * 2;
                float v0 = c[mt][nt][i * 2 + 0] + bias[col];
                float v1 = c[mt][nt][i * 2 + 1] + bias[col + 1];
                if (isSel) {
                    v0 = 1.0f / (1.0f + expf(-v0));
                    v1 = 1.0f / (1.0f + expf(-v1));
                }
                *reinterpret_cast<float2*>(out + (size_t)gr * D + col) = make_float2(v0, v1);
            }
        }
    }
}

// ---------------- block reduce ----------------
__device__ __forceinline__ float blockReduceSum256(float v) {
    __shared__ float sh[8];
    __shared__ float s_tot;
    int lane = threadIdx.x & 31;
    int wid = threadIdx.x >> 5;
    #pragma unroll
    for (int o = 16; o > 0; o >>= 1) v += __shfl_down_sync(0xffffffffu, v, o);
    if (lane == 0) sh[wid] = v;
    __syncthreads();
    if (wid == 0) {
        float t = (lane < 8) ? sh[lane] : 0.0f;
        #pragma unroll
        for (int o = 4; o > 0; o >>= 1) t += __shfl_down_sync(0xffffffffu, t, o);
        if (lane == 0) s_tot = t;
    }
    __syncthreads();
    return s_tot;
}

__global__ void rmsnorm_k(const float* __restrict__ xp, const float* __restrict__ w,
                          float* __restrict__ xn) {
    const int r = blockIdx.x;
    const float* row = xp + (size_t)r * D;
    float ss = 0.0f;
    for (int d = threadIdx.x; d < D; d += 256) { float v = row[d]; ss += v * v; }
    float tot = blockReduceSum256(ss);
    float inv = 1.0f / sqrtf(tot / (float)D + EPSV);
    for (int d = threadIdx.x; d < D; d += 256)
        xn[(size_t)r * D + d] = row[d] * inv * w[d];
}

// LIF: 64-tap FIR == recurrence with 63-step warm start per 256-step chunk.
__global__ void lif_chunk(const float* __restrict__ xn, float* __restrict__ spk,
                          const float* __restrict__ tau_a, const float* __restrict__ th_a,
                          int Tn, int nchunks) {
    int idx = blockIdx.x * 256 + threadIdx.x;
    int total = BATCH * D * nchunks;
    if (idx >= total) return;
    int d = idx % D;
    int rest = idx / D;
    int chunk = rest % nchunks;
    int b = rest / nchunks;
    float tau = tau_a[d], th = th_a[d];
    const float* col = xn + (size_t)b * Tn * D + d;
    float* so = spk + (size_t)b * Tn * D + d;
    int t0 = chunk * 256;
    int tend = t0 + 256; if (tend > Tn) tend = Tn;
    int ws = t0 - 63; if (ws < 0) ws = 0;
    float v = 0.0f;
    for (int t = ws; t < t0; t++) v = fmaf(tau, v, col[(size_t)t * D]);
    for (int t = t0; t < tend; t++) {
        v = fmaf(tau, v, col[(size_t)t * D]);
        so[(size_t)t * D] = (v >= th) ? 1.0f : 0.0f;
    }
}

// ---------------- combines ----------------
__global__ void combine_up(const float* __restrict__ xp, const float* __restrict__ gt,
                           const float* __restrict__ spk, const float* __restrict__ cur,
                           float* __restrict__ outS) {
    const int r = blockIdx.x;
    float s = 0.0f;
    for (int d = threadIdx.x; d < D; d += 256) s += spk[(size_t)r * D + d];
    float denom = blockReduceSum256(s);
    denom = denom > 1.0f ? denom : 1.0f;
    for (int d = threadIdx.x; d < D; d += 256) {
        size_t o = (size_t)r * D + d;
        float g = gt[o];
        float lifout = xp[o] + spk[o] / denom;
        float res = 0.5f * (cur[(size_t)r * K2 + d] + cur[(size_t)r * K2 + D + d]);
        outS[o] = g * lifout + (1.0f - g) * res;
    }
}

__global__ void combine_down(const float* __restrict__ xp, const float* __restrict__ gt,
                             const float* __restrict__ spk, const float* __restrict__ ctx,
                             float* __restrict__ ctxN) {
    const int r = blockIdx.x;
    float s = 0.0f;
    for (int d = threadIdx.x; d < D; d += 256) s += spk[(size_t)r * D + d];
    float denom = blockReduceSum256(s);
    denom = denom > 1.0f ? denom : 1.0f;
    for (int d = threadIdx.x; d < D; d += 256) {
        size_t o = (size_t)r * D + d;
        float c = ctx[o];
        float g = gt[o];
        float lifout = xp[o] + spk[o] / denom;
        float cr = g * lifout + (1.0f - g) * c;
        ctxN[(size_t)(2 * r) * D + d] = c;
        ctxN[(size_t)(2 * r + 1) * D + d] = cr;
    }
}

__global__ void combine_leaf(const float* __restrict__ xp, const float* __restrict__ gt,
                             const float* __restrict__ spk, const float* __restrict__ x,
                             float* __restrict__ out) {
    const int r = blockIdx.x;
    float s = 0.0f;
    for (int d = threadIdx.x; d < D; d += 256) s += spk[(size_t)r * D + d];
    float denom = blockReduceSum256(s);
    denom = denom > 1.0f ? denom : 1.0f;
    for (int d = threadIdx.x; d < D; d += 256) {
        size_t o = (size_t)r * D + d;
        float g = gt[o];
        float lifout = xp[o] + spk[o] / denom;
        out[o] = g * lifout + (1.0f - g) * x[o];
    }
}

__global__ void zero_k(float* __restrict__ p, int n) {
    int i = blockIdx.x * 256 + threadIdx.x;
    if (i < n) p[i] = 0.0f;
}

// ---------------- launcher ----------------
extern "C" void kernel_launch(void* const* d_in, const int* in_sizes, int n_in,
                              void* d_out, int out_size) {
    const float* x     = (const float*)d_in[0];
    const float* upW   = (const float*)d_in[1];
    const float* upB   = (const float*)d_in[2];
    const float* upSW  = (const float*)d_in[3];
    const float* upSB  = (const float*)d_in[4];
    const float* upNW  = (const float*)d_in[5];
    const float* upTH  = (const float*)d_in[6];
    const float* upTAU = (const float*)d_in[7];
    const float* dnW   = (const float*)d_in[8];
    const float* dnB   = (const float*)d_in[9];
    const float* dnSW  = (const float*)d_in[10];
    const float* dnSB  = (const float*)d_in[11];
    const float* dnNW  = (const float*)d_in[12];
    const float* dnTH  = (const float*)d_in[13];
    const float* dnTAU = (const float*)d_in[14];
    const float* lfSW  = (const float*)d_in[15];
    const float* lfSB  = (const float*)d_in[16];
    const float* lfW   = (const float*)d_in[17];
    const float* lfB   = (const float*)d_in[18];
    const float* lfNW  = (const float*)d_in[19];
    const float* lfTH  = (const float*)d_in[20];
    const float* lfTAU = (const float*)d_in[21];
    float* out = (float*)d_out;

    float *S, *cA, *cB, *XP, *GT, *XN, *SPK;
    cudaGetSymbolAddress((void**)&S, g_S);
    cudaGetSymbolAddress((void**)&cA, g_ctxA);
    cudaGetSymbolAddress((void**)&cB, g_ctxB);
    cudaGetSymbolAddress((void**)&XP, g_XP);
    cudaGetSymbolAddress((void**)&GT, g_GT);
    cudaGetSymbolAddress((void**)&XN, g_XN);
    cudaGetSymbolAddress((void**)&SPK, g_SPK);

    // shared mem: A = 3*128*36, B128 = 3*32*136, B64 = 3*32*72 floats
    const int SMEM128 = (3 * 128 * 36 + 3 * 32 * 136) * 4;   // 107,520
    const int SMEM64  = (3 * 128 * 36 + 3 * 32 * 72) * 4;    //  82,944
    cudaFuncSetAttribute(gemm_mma<128, 2>, cudaFuncAttributeMaxDynamicSharedMemorySize, SMEM128);
    cudaFuncSetAttribute(gemm_mma<64, 4>,  cudaFuncAttributeMaxDynamicSharedMemorySize, SMEM64);

    auto launch_gemm = [&](const float* A0, int ldA0, const float* A1, int ldA1,
                           const float* Wpp, const float* Wss,
                           const float* bpp, const float* bss, int M) {
        if (M >= 512) {
            dim3 g(12, (M + 127) / 128);
            gemm_mma<128, 2><<<g, 256, SMEM128>>>(A0, ldA0, A1, ldA1, Wpp, Wss, bpp, bss, XP, GT, M);
        } else {
            dim3 g(24, (M + 127) / 128);
            gemm_mma<64, 4><<<g, 256, SMEM64>>>(A0, ldA0, A1, ldA1, Wpp, Wss, bpp, bss, XP, GT, M);
        }
    };

    size_t soff[NLEV + 1];
    soff[1] = 0;
    for (int k = 1; k < NLEV; k++)
        soff[k + 1] = soff[k] + (size_t)BATCH * (TSEQ >> k) * D;

    // ---- up pass ----
    const float* cur = x;
    int Tl = TSEQ;
    for (int l = 0; l < NLEV; l++) {
        int Tn = Tl >> 1;
        int M = BATCH * Tn;
        float* Sout = S + soff[l + 1];
        launch_gemm(cur, K2, cur + D, K2,
                    upW + (size_t)l * K2 * D, upSW + (size_t)l * K2 * D,
                    upB + (size_t)l * D, upSB + (size_t)l * D, M);
        rmsnorm_k<<<M, 256>>>(XP, upNW + (size_t)l * D, XN);
        int nch = (Tn + 255) / 256;
        int tot = BATCH * D * nch;
        lif_chunk<<<(tot + 255) / 256, 256>>>(XN, SPK, upTAU + (size_t)l * D,
                                              upTH + (size_t)l * D, Tn, nch);
        combine_up<<<M, 256>>>(XP, GT, SPK, cur, Sout);
        cur = Sout;
        Tl = Tn;
    }

    // ---- down pass ----
    zero_k<<<(BATCH * D + 255) / 256, 256>>>(cA, BATCH * D);
    float* ctx = cA;
    float* ctxN = cB;
    int n = 1;
    for (int l = NLEV; l >= 1; l--) {
        int i = l - 1;
        int M = BATCH * n;
        const float* child = (i == 0) ? x : (S + soff[i]);
        launch_gemm(ctx, D, child, 2 * D,
                    dnW + (size_t)i * K2 * D, dnSW + (size_t)i * K2 * D,
                    dnB + (size_t)i * D, dnSB + (size_t)i * D, M);
        rmsnorm_k<<<M, 256>>>(XP, dnNW + (size_t)i * D, XN);
        int nch = (n + 255) / 256;
        int tot = BATCH * D * nch;
        lif_chunk<<<(tot + 255) / 256, 256>>>(XN, SPK, dnTAU + (size_t)i * D,
                                              dnTH + (size_t)i * D, n, nch);
        combine_down<<<M, 256>>>(XP, GT, SPK, ctx, ctxN);
        float* tmp = ctx; ctx = ctxN; ctxN = tmp;
        n <<= 1;
    }

    // ---- leaf fusion ----
    {
        int M = BATCH * TSEQ;
        launch_gemm(x, D, ctx, D, lfW, lfSW, lfB, lfSB, M);
        rmsnorm_k<<<M, 256>>>(XP, lfNW, XN);
        int nch = (TSEQ + 255) / 256;
        int tot = BATCH * D * nch;
        lif_chunk<<<(tot + 255) / 256, 256>>>(XN, SPK, lfTAU, lfTH, TSEQ, nch);
        combine_leaf<<<M, 256>>>(XP, GT, SPK, x, out);
    }
}